// round 7
// baseline (speedup 1.0000x reference)
#include <cuda_runtime.h>
#include <cstdint>

// ---------------- problem constants ----------------
#define BW    1024
#define SEQ   144
#define CH    512
#define NH    16
#define DH    32
#define NWIN  64
#define MROWS (BW*SEQ)          // 147456
#define LOG100 4.6051701859880913680f

// ---------------- scratch (device globals; no cudaMalloc allowed) ----------
__device__ float g_qkv[(size_t)MROWS * 1536];   // q|k|v concatenated per row (fp32)
__device__ float g_att[(size_t)MROWS * 512];    // attention out, tf32-rounded
__device__ float g_xt[(size_t)MROWS * 512];     // x rounded to tf32
__device__ float g_wt[4 * 512 * 512];           // Wq|Wk|Wv|Wp rounded to tf32

// ---------------- helpers ----------------
__device__ __forceinline__ uint32_t f2tf32(float f) {
    uint32_t u;
    asm("cvt.rna.tf32.f32 %0, %1;" : "=r"(u) : "f"(f));
    return u;
}
__device__ __forceinline__ float rtf(float f) { return __uint_as_float(f2tf32(f)); }

__device__ __forceinline__ uint32_t smem_u32(const void* p) {
    uint32_t a;
    asm("{ .reg .u64 t; cvta.to.shared.u64 t, %1; cvt.u32.u64 %0, t; }" : "=r"(a) : "l"(p));
    return a;
}

__device__ __forceinline__ void mma8(float* c, const uint32_t* a, uint32_t b0, uint32_t b1) {
    asm volatile(
        "mma.sync.aligned.m16n8k8.row.col.f32.tf32.tf32.f32 "
        "{%0,%1,%2,%3}, {%4,%5,%6,%7}, {%8,%9}, {%0,%1,%2,%3};\n"
        : "+f"(c[0]), "+f"(c[1]), "+f"(c[2]), "+f"(c[3])
        : "r"(a[0]), "r"(a[1]), "r"(a[2]), "r"(a[3]), "r"(b0), "r"(b1));
}

__device__ __forceinline__ void cp16(uint32_t dst, const void* src) {
    asm volatile("cp.async.cg.shared.global [%0], [%1], 16;" :: "r"(dst), "l"(src));
}

// ============================================================
// GEMM: C[m, z*512 + n] = A[m,:] . B_z[n,:] + bias_z[n]
// (unchanged from round 6)
// ============================================================
#define APAD 36
#define AS_OFF(s) ((s) * 128 * APAD)
#define BS_OFF(s) (2 * 128 * APAD + (s) * 128 * APAD)
#define GEMM_SMEM (4 * 128 * APAD * 4)   // 73728 B

__global__ void __launch_bounds__(128, 3)
gemm_tf32_kernel(const float* __restrict__ A,
                 const float* __restrict__ B0, const float* __restrict__ B1,
                 const float* __restrict__ B2,
                 const float* __restrict__ bias0, const float* __restrict__ bias1,
                 const float* __restrict__ bias2,
                 float* __restrict__ Cout, int ldc)
{
    const int z  = blockIdx.x >> 2;
    const int nb = blockIdx.x & 3;
    const float* B    = (z == 0) ? B0 : (z == 1 ? B1 : B2);
    const float* bias = (z == 0) ? bias0 : (z == 1 ? bias1 : bias2);

    const int m0 = blockIdx.y * 128;
    const int n0 = nb * 128;

    extern __shared__ uint32_t smem_u[];
    const uint32_t sb = smem_u32(smem_u);

    const int tid  = threadIdx.x;
    const int warp = tid >> 5, lane = tid & 31;
    const int wm = warp & 1;
    const int wn = warp >> 1;
    const int g  = lane >> 2, tg = lane & 3;

    const int r8 = tid >> 3;
    const int c4 = (tid & 7) * 4;

    const float* Abase = A + (size_t)(m0 + r8) * 512 + c4;
    const float* Bbase = B + (size_t)(n0 + r8) * 512 + c4;

    float acc[4][8][4];
#pragma unroll
    for (int i = 0; i < 4; i++)
#pragma unroll
        for (int j = 0; j < 8; j++)
#pragma unroll
            for (int r = 0; r < 4; r++) acc[i][j][r] = 0.f;

#pragma unroll
    for (int s = 0; s < 2; s++) {
        uint32_t ad = sb + (AS_OFF(s) + r8 * APAD + c4) * 4;
        uint32_t bd = sb + (BS_OFF(s) + r8 * APAD + c4) * 4;
#pragma unroll
        for (int i = 0; i < 8; i++) {
            cp16(ad + i * 16 * APAD * 4, Abase + s * 32 + (size_t)i * 16 * 512);
            cp16(bd + i * 16 * APAD * 4, Bbase + s * 32 + (size_t)i * 16 * 512);
        }
        asm volatile("cp.async.commit_group;" ::: "memory");
    }

#pragma unroll 1
    for (int kt = 0; kt < 16; kt++) {
        const int s = kt & 1;
        if (kt < 15)
            asm volatile("cp.async.wait_group 1;" ::: "memory");
        else
            asm volatile("cp.async.wait_group 0;" ::: "memory");
        __syncthreads();

        const uint32_t* Ab = smem_u + AS_OFF(s);
        const uint32_t* Bb = smem_u + BS_OFF(s);
#pragma unroll
        for (int ks = 0; ks < 4; ks++) {
            uint32_t af[4][4];
#pragma unroll
            for (int mi = 0; mi < 4; mi++) {
                const uint32_t* p = Ab + (wm * 64 + mi * 16 + g) * APAD + ks * 8 + tg;
                af[mi][0] = p[0];
                af[mi][2] = p[4];
                af[mi][1] = p[8 * APAD];
                af[mi][3] = p[8 * APAD + 4];
            }
#pragma unroll
            for (int ni = 0; ni < 8; ni++) {
                const uint32_t* p = Bb + (wn * 64 + ni * 8 + g) * APAD + ks * 8 + tg;
                uint32_t b0 = p[0], b1 = p[4];
#pragma unroll
                for (int mi = 0; mi < 4; mi++)
                    mma8(acc[mi][ni], af[mi], b0, b1);
            }
        }
        __syncthreads();

        if (kt + 2 < 16) {
            uint32_t ad = sb + (AS_OFF(s) + r8 * APAD + c4) * 4;
            uint32_t bd = sb + (BS_OFF(s) + r8 * APAD + c4) * 4;
#pragma unroll
            for (int i = 0; i < 8; i++) {
                cp16(ad + i * 16 * APAD * 4, Abase + (kt + 2) * 32 + (size_t)i * 16 * 512);
                cp16(bd + i * 16 * APAD * 4, Bbase + (kt + 2) * 32 + (size_t)i * 16 * 512);
            }
            asm volatile("cp.async.commit_group;" ::: "memory");
        }
    }

#pragma unroll
    for (int mi = 0; mi < 4; mi++) {
        int row = m0 + wm * 64 + mi * 16 + g;
#pragma unroll
        for (int ni = 0; ni < 8; ni++) {
            int ncol = n0 + wn * 64 + ni * 8 + 2 * tg;
            int gcol = z * 512 + ncol;
            float b0 = bias[ncol], b1 = bias[ncol + 1];
            float2 v0 = make_float2(acc[mi][ni][0] + b0, acc[mi][ni][1] + b1);
            float2 v1 = make_float2(acc[mi][ni][2] + b0, acc[mi][ni][3] + b1);
            *(float2*)(Cout + (size_t)row * ldc + gcol) = v0;
            *(float2*)(Cout + (size_t)(row + 8) * ldc + gcol) = v1;
        }
    }
}

// ============================================================
// conversion kernels (fp32 -> tf32-rounded fp32 in global)
// ============================================================
__global__ void convert_x_kernel(const float* __restrict__ x, float* __restrict__ o)
{
    size_t i = (size_t)blockIdx.x * 256 + threadIdx.x;
    float4 v = ((const float4*)x)[i];
    ((uint4*)o)[i] = make_uint4(f2tf32(v.x), f2tf32(v.y), f2tf32(v.z), f2tf32(v.w));
}

__global__ void convert_w_kernel(const float* __restrict__ w0, const float* __restrict__ w1,
                                 const float* __restrict__ w2, const float* __restrict__ w3,
                                 float* __restrict__ o)
{
    size_t i = (size_t)blockIdx.x * 256 + threadIdx.x;
    const float* srcs[4] = {w0, w1, w2, w3};
#pragma unroll
    for (int m = 0; m < 4; m++) {
        float4 v = ((const float4*)srcs[m])[i];
        ((uint4*)(o + (size_t)m * 262144))[i] =
            make_uint4(f2tf32(v.x), f2tf32(v.y), f2tf32(v.z), f2tf32(v.w));
    }
}

// ============================================================
// Attention: flash online softmax, 5 warps x 32 q-rows (mi=2),
// rows padded 144->160 (warp4/mi1 phantom: Q=0, mask clamped, no store).
// S via 3-term tf32 split; PV(s-1) deferred into strip s to overlap
// with softmax shuffles; P strips stored as conflict-free STS.64.
// ============================================================
#define KP 36
#define VP 40
#define SP 36
#define ATT_SMEM_WORDS (2*144*KP + 144*VP + 5*32*SP)   // 21888 words = 87552 B

__device__ __forceinline__ void compute_strip2(
    const uint32_t* __restrict__ ksh, const uint32_t* __restrict__ ksl,
    const uint32_t (&ah)[2][4][4], const uint32_t (&al)[2][4][4],
    int g, int tg, int s, float (&sacc)[2][3][4])
{
#pragma unroll
    for (int j = 0; j < 3; j++) {
#pragma unroll
        for (int r = 0; r < 4; r++) { sacc[0][j][r] = 0.f; sacc[1][j][r] = 0.f; }
        const int nt = 3 * s + j;
#pragma unroll
        for (int kt = 0; kt < 4; kt++) {
            const uint32_t* p = ksh + (nt * 8 + g) * KP + kt * 8 + tg;
            uint32_t bh0 = p[0], bh1 = p[4];
            const uint32_t* q = ksl + (nt * 8 + g) * KP + kt * 8 + tg;
            uint32_t bl0 = q[0], bl1 = q[4];
#pragma unroll
            for (int mi = 0; mi < 2; mi++) {
                mma8(sacc[mi][j], ah[mi][kt], bh0, bh1);
                mma8(sacc[mi][j], al[mi][kt], bh0, bh1);
                mma8(sacc[mi][j], ah[mi][kt], bl0, bl1);
            }
        }
    }
}

__global__ void __launch_bounds__(160, 2)
attn_kernel(const float* __restrict__ mask,
            const float* __restrict__ logit_scale,
            float* __restrict__ attout)
{
    const int bh = blockIdx.x;
    const int b = bh >> 4;
    const int h = bh & 15;
    const int win = b & (NWIN - 1);

    const int tid = threadIdx.x;
    const int w = tid >> 5, lane = tid & 31;
    const int g = lane >> 2, tg = lane & 3;

    extern __shared__ uint32_t sm_u[];
    uint32_t* ksh = sm_u;                    // [144][KP]
    uint32_t* ksl = ksh + 144 * KP;          // [144][KP]
    uint32_t* vsm = ksl + 144 * KP;          // [144][VP]
    uint32_t* pstrip = vsm + 144 * VP;       // [5][32][SP]

    const float scale = expf(fminf(logit_scale[h], LOG100));

    const float* qbase = g_qkv + (size_t)(b * SEQ) * 1536 + h * 32;
    const float* kbase = qbase + 512;
    const float* vbase = qbase + 1024;

    // ---- load K (normalized, hi/lo split) and V (tf32), 2 threads/row ----
#pragma unroll
    for (int t = tid; t < 288; t += 160) {
        int r = t >> 1, half = t & 1;
        const float4* kr = (const float4*)(kbase + (size_t)r * 1536 + half * 16);
        float kv[16];
        float sq = 0.f;
#pragma unroll
        for (int i4 = 0; i4 < 4; i4++) {
            float4 f = kr[i4];
            kv[i4*4+0] = f.x; kv[i4*4+1] = f.y; kv[i4*4+2] = f.z; kv[i4*4+3] = f.w;
            sq += f.x*f.x + f.y*f.y + f.z*f.z + f.w*f.w;
        }
        sq += __shfl_xor_sync(0xffffffffu, sq, 1);
        float inv = 1.f / fmaxf(sqrtf(sq), 1e-12f);
#pragma unroll
        for (int i = 0; i < 16; i++) {
            int d = half * 16 + i;
            float f = kv[i] * inv;
            uint32_t hi = f2tf32(f);
            float lo = f - __uint_as_float(hi);
            ksh[r * KP + d] = hi;
            ksl[r * KP + d] = f2tf32(lo);
        }
        const float4* vr = (const float4*)(vbase + (size_t)r * 1536 + half * 16);
#pragma unroll
        for (int i4 = 0; i4 < 4; i4++) {
            float4 f = vr[i4];
            int d = half * 16 + i4 * 4;
            vsm[r * VP + d + 0] = f2tf32(f.x);
            vsm[r * VP + d + 1] = f2tf32(f.y);
            vsm[r * VP + d + 2] = f2tf32(f.z);
            vsm[r * VP + d + 3] = f2tf32(f.w);
        }
    }

    // ---- Q fragments from global, per mi tile (rows 32w+16mi+{g,g+8}) ----
    uint32_t ah[2][4][4], al[2][4][4];
    const float NEG_INF = __int_as_float(0xff800000);
#pragma unroll
    for (int mi = 0; mi < 2; mi++) {
        const int rA = w * 32 + mi * 16 + g;
        const int rB = rA + 8;
        float q0[8], q1[8];
        float sq0 = 0.f, sq1 = 0.f;
        const float* qr0 = qbase + (size_t)rA * 1536 + tg;
        const float* qr1 = qbase + (size_t)rB * 1536 + tg;
#pragma unroll
        for (int i = 0; i < 8; i++) {
            q0[i] = (rA < 144) ? qr0[4 * i] : 0.f;
            q1[i] = (rB < 144) ? qr1[4 * i] : 0.f;
            sq0 += q0[i] * q0[i];
            sq1 += q1[i] * q1[i];
        }
        sq0 += __shfl_xor_sync(0xffffffffu, sq0, 1);
        sq0 += __shfl_xor_sync(0xffffffffu, sq0, 2);
        sq1 += __shfl_xor_sync(0xffffffffu, sq1, 1);
        sq1 += __shfl_xor_sync(0xffffffffu, sq1, 2);
        float inv0 = scale / fmaxf(sqrtf(sq0), 1e-12f);
        float inv1 = scale / fmaxf(sqrtf(sq1), 1e-12f);
#pragma unroll
        for (int kt = 0; kt < 4; kt++) {
            float f;
            f = q0[2 * kt] * inv0;
            ah[mi][kt][0] = f2tf32(f);
            al[mi][kt][0] = f2tf32(f - __uint_as_float(ah[mi][kt][0]));
            f = q0[2 * kt + 1] * inv0;
            ah[mi][kt][2] = f2tf32(f);
            al[mi][kt][2] = f2tf32(f - __uint_as_float(ah[mi][kt][2]));
            f = q1[2 * kt] * inv1;
            ah[mi][kt][1] = f2tf32(f);
            al[mi][kt][1] = f2tf32(f - __uint_as_float(ah[mi][kt][1]));
            f = q1[2 * kt + 1] * inv1;
            ah[mi][kt][3] = f2tf32(f);
            al[mi][kt][3] = f2tf32(f - __uint_as_float(ah[mi][kt][3]));
        }
    }
    __syncthreads();   // K/V smem ready

    // ---- online softmax state (per mi) ----
    float mr[2][2]  = {{NEG_INF, NEG_INF}, {NEG_INF, NEG_INF}};  // [mi][rowA/rowB]
    float sr[2][2]  = {{0.f, 0.f}, {0.f, 0.f}};
    float oc[2][4][4];
#pragma unroll
    for (int mi = 0; mi < 2; mi++)
#pragma unroll
        for (int nt = 0; nt < 4; nt++)
#pragma unroll
            for (int r = 0; r < 4; r++) oc[mi][nt][r] = 0.f;

    uint32_t* pw = pstrip + w * 32 * SP;
    const float* mbase = mask + (size_t)win * SEQ * SEQ + 2 * tg;
    // clamped mask row pointers (phantom rows read row 143; values unused)
    const float* mrow[2][2];
#pragma unroll
    for (int mi = 0; mi < 2; mi++) {
        int rA = w * 32 + mi * 16 + g;
        int rB = rA + 8;
        mrow[mi][0] = mbase + (size_t)(rA < 144 ? rA : 143) * SEQ;
        mrow[mi][1] = mbase + (size_t)(rB < 144 ? rB : 143) * SEQ;
    }

    float sacc[2][3][4];

#pragma unroll
    for (int s = 0; s < 6; s++) {
        // S(s) = Q . K^T (3-term split)
        compute_strip2(ksh, ksl, ah, al, g, tg, s, sacc);

        // masks
        float2 mk[2][2][3];
#pragma unroll
        for (int mi = 0; mi < 2; mi++)
#pragma unroll
            for (int j = 0; j < 3; j++) {
                mk[mi][0][j] = *(const float2*)(mrow[mi][0] + (3 * s + j) * 8);
                mk[mi][1][j] = *(const float2*)(mrow[mi][1] + (3 * s + j) * 8);
            }

        // mask add + strip max
        float mx[2][2];
#pragma unroll
        for (int mi = 0; mi < 2; mi++) {
            mx[mi][0] = NEG_INF; mx[mi][1] = NEG_INF;
#pragma unroll
            for (int j = 0; j < 3; j++) {
                sacc[mi][j][0] += mk[mi][0][j].x; sacc[mi][j][1] += mk[mi][0][j].y;
                sacc[mi][j][2] += mk[mi][1][j].x; sacc[mi][j][3] += mk[mi][1][j].y;
                mx[mi][0] = fmaxf(mx[mi][0], fmaxf(sacc[mi][j][0], sacc[mi][j][1]));
                mx[mi][1] = fmaxf(mx[mi][1], fmaxf(sacc[mi][j][2], sacc[mi][j][3]));
            }
            mx[mi][0] = fmaxf(mx[mi][0], __shfl_xor_sync(0xffffffffu, mx[mi][0], 1));
            mx[mi][0] = fmaxf(mx[mi][0], __shfl_xor_sync(0xffffffffu, mx[mi][0], 2));
            mx[mi][1] = fmaxf(mx[mi][1], __shfl_xor_sync(0xffffffffu, mx[mi][1], 1));
            mx[mi][1] = fmaxf(mx[mi][1], __shfl_xor_sync(0xffffffffu, mx[mi][1], 2));
        }

        // deferred PV(s-1): oc += P(s-1) @ V  (independent of the shuffles above)
        if (s > 0) {
            const int key0 = (s - 1) * 24;
#pragma unroll
            for (int kt2 = 0; kt2 < 3; kt2++) {
                uint32_t a[2][4];
#pragma unroll
                for (int mi = 0; mi < 2; mi++) {
                    const uint32_t* p = pw + (mi * 16 + g) * SP + kt2 * 8 + tg;
                    a[mi][0] = p[0]; a[mi][2] = p[4];
                    const uint32_t* p2 = p + 8 * SP;
                    a[mi][1] = p2[0]; a[mi][3] = p2[4];
                }
#pragma unroll
                for (int nt = 0; nt < 4; nt++) {
                    uint32_t b0 = vsm[(key0 + kt2 * 8 + tg) * VP + nt * 8 + g];
                    uint32_t b1 = vsm[(key0 + kt2 * 8 + tg + 4) * VP + nt * 8 + g];
#pragma unroll
                    for (int mi = 0; mi < 2; mi++)
                        mma8(oc[mi][nt], a[mi], b0, b1);
                }
            }
        }
        __syncwarp();

        // rescale, exp, sums, store P(s)
#pragma unroll
        for (int mi = 0; mi < 2; mi++) {
            float mn0 = fmaxf(mr[mi][0], mx[mi][0]);
            float mn1 = fmaxf(mr[mi][1], mx[mi][1]);
            float f0 = __expf(mr[mi][0] - mn0);
            float f1 = __expf(mr[mi][1] - mn1);
            mr[mi][0] = mn0; mr[mi][1] = mn1;
            sr[mi][0] *= f0; sr[mi][1] *= f1;
#pragma unroll
            for (int nt = 0; nt < 4; nt++) {
                oc[mi][nt][0] *= f0; oc[mi][nt][1] *= f0;
                oc[mi][nt][2] *= f1; oc[mi][nt][3] *= f1;
            }
#pragma unroll
            for (int j = 0; j < 3; j++) {
                float p0 = __expf(sacc[mi][j][0] - mn0);
                float p1 = __expf(sacc[mi][j][1] - mn0);
                float p2 = __expf(sacc[mi][j][2] - mn1);
                float p3 = __expf(sacc[mi][j][3] - mn1);
                sr[mi][0] += p0 + p1;
                sr[mi][1] += p2 + p3;
                uint32_t* d0 = pw + (mi * 16 + g) * SP + j * 8 + 2 * tg;
                *(uint2*)d0 = make_uint2(f2tf32(p0), f2tf32(p1));
                uint32_t* d1 = pw + (mi * 16 + g + 8) * SP + j * 8 + 2 * tg;
                *(uint2*)d1 = make_uint2(f2tf32(p2), f2tf32(p3));
            }
        }
        __syncwarp();
    }

    // final PV(5)
    {
        const int key0 = 5 * 24;
#pragma unroll
        for (int kt2 = 0; kt2 < 3; kt2++) {
            uint32_t a[2][4];
#pragma unroll
            for (int mi = 0; mi < 2; mi++) {
                const uint32_t* p = pw + (mi * 16 + g) * SP + kt2 * 8 + tg;
                a[mi][0] = p[0]; a[mi][2] = p[4];
                const uint32_t* p2 = p + 8 * SP;
                a[mi][1] = p2[0]; a[mi][3] = p2[4];
            }
#pragma unroll
            for (int nt = 0; nt < 4; nt++) {
                uint32_t b0 = vsm[(key0 + kt2 * 8 + tg) * VP + nt * 8 + g];
                uint32_t b1 = vsm[(key0 + kt2 * 8 + tg + 4) * VP + nt * 8 + g];
#pragma unroll
                for (int mi = 0; mi < 2; mi++)
                    mma8(oc[mi][nt], a[mi], b0, b1);
            }
        }
    }

    // ---- finalize & store (skip phantom rows) ----
#pragma unroll
    for (int mi = 0; mi < 2; mi++) {
        float s0 = sr[mi][0], s1 = sr[mi][1];
        s0 += __shfl_xor_sync(0xffffffffu, s0, 1);
        s0 += __shfl_xor_sync(0xffffffffu, s0, 2);
        s1 += __shfl_xor_sync(0xffffffffu, s1, 1);
        s1 += __shfl_xor_sync(0xffffffffu, s1, 2);
        float inv0 = 1.f / s0, inv1 = 1.f / s1;

        const int rA = w * 32 + mi * 16 + g;
        if (rA < 144) {
            const int row0 = b * SEQ + rA;
#pragma unroll
            for (int nt = 0; nt < 4; nt++) {
                int col = h * 32 + nt * 8 + 2 * tg;
                *(float2*)(attout + (size_t)row0 * 512 + col) =
                    make_float2(rtf(oc[mi][nt][0] * inv0), rtf(oc[mi][nt][1] * inv0));
                *(float2*)(attout + (size_t)(row0 + 8) * 512 + col) =
                    make_float2(rtf(oc[mi][nt][2] * inv1), rtf(oc[mi][nt][3] * inv1));
            }
        }
    }
}

// ============================================================
// launch
// ============================================================
extern "C" void kernel_launch(void* const* d_in, const int* in_sizes, int n_in,
                              void* d_out, int out_size)
{
    (void)in_sizes; (void)n_in; (void)out_size;
    const float* x    = (const float*)d_in[0];
    const float* mask = (const float*)d_in[1];
    const float* Wq   = (const float*)d_in[2];
    const float* bq   = (const float*)d_in[3];
    const float* Wk   = (const float*)d_in[4];
    const float* bk   = (const float*)d_in[5];
    const float* Wv   = (const float*)d_in[6];
    const float* bv   = (const float*)d_in[7];
    const float* Wp   = (const float*)d_in[8];
    const float* bp   = (const float*)d_in[9];
    const float* ls   = (const float*)d_in[10];
    float* out = (float*)d_out;

    void *qkv_p = nullptr, *att_p = nullptr, *xt_p = nullptr, *wt_p = nullptr;
    cudaGetSymbolAddress(&qkv_p, g_qkv);
    cudaGetSymbolAddress(&att_p, g_att);
    cudaGetSymbolAddress(&xt_p, g_xt);
    cudaGetSymbolAddress(&wt_p, g_wt);
    float* qkv = (float*)qkv_p;
    float* att = (float*)att_p;
    float* xt  = (float*)xt_p;
    float* wt  = (float*)wt_p;

    const int att_smem = ATT_SMEM_WORDS * 4;               // 87552 B
    cudaFuncSetAttribute(gemm_tf32_kernel,
                         cudaFuncAttributeMaxDynamicSharedMemorySize, GEMM_SMEM);
    cudaFuncSetAttribute(attn_kernel,
                         cudaFuncAttributeMaxDynamicSharedMemorySize, att_smem);

    // 0) round inputs to tf32 (in global)
    convert_x_kernel<<<MROWS * 512 / 4 / 256, 256>>>(x, xt);
    convert_w_kernel<<<256, 256>>>(Wq, Wk, Wv, Wp, wt);

    // 1) QKV projections: grid.x = 4 n-tiles * 3 z
    gemm_tf32_kernel<<<dim3(12, MROWS / 128), 128, GEMM_SMEM>>>(
        xt, wt, wt + 262144, wt + 2 * 262144, bq, bk, bv, qkv, 1536);

    // 2) attention (flash, mi=2 warp tiles, deferred PV overlap)
    attn_kernel<<<BW * NH, 160, att_smem>>>(mask, ls, att);

    // 3) output projection
    gemm_tf32_kernel<<<dim3(4, MROWS / 128), 128, GEMM_SMEM>>>(
        att, wt + 3 * 262144, wt + 3 * 262144, wt + 3 * 262144, bp, bp, bp, out, 512);
}

// round 8
// speedup vs baseline: 1.2885x; 1.2885x over previous
#include <cuda_runtime.h>
#include <cuda_fp16.h>
#include <cstdint>

// ---------------- problem constants ----------------
#define BW    1024
#define SEQ   144
#define CH    512
#define NH    16
#define DH    32
#define NWIN  64
#define MROWS (BW*SEQ)          // 147456
#define LOG100 4.6051701859880913680f

// ---------------- scratch (device globals; no cudaMalloc allowed) ----------
__device__ float  g_qkv[(size_t)MROWS * 1536];   // q|k|v per row (fp32, from QKV gemm)
__device__ __half g_atth[(size_t)MROWS * 512];   // attention out (fp16)
__device__ __half g_xh[(size_t)MROWS * 512];     // x rounded to fp16
__device__ __half g_wh[4 * 512 * 512];           // Wq|Wk|Wv|Wp rounded to fp16

// ---------------- helpers ----------------
__device__ __forceinline__ uint32_t pack2h(float x, float y) {
    __half2 h = __floats2half2_rn(x, y);
    return *(uint32_t*)&h;
}
__device__ __forceinline__ float2 unpack2h(uint32_t u) {
    __half2 h = *(__half2*)&u;
    return __half22float2(h);
}

__device__ __forceinline__ uint32_t smem_u32(const void* p) {
    uint32_t a;
    asm("{ .reg .u64 t; cvta.to.shared.u64 t, %1; cvt.u32.u64 %0, t; }" : "=r"(a) : "l"(p));
    return a;
}

// fp16 mma m16n8k16, fp32 accumulate
__device__ __forceinline__ void mma16(float* c, const uint32_t* a, uint32_t b0, uint32_t b1) {
    asm volatile(
        "mma.sync.aligned.m16n8k16.row.col.f32.f16.f16.f32 "
        "{%0,%1,%2,%3}, {%4,%5,%6,%7}, {%8,%9}, {%0,%1,%2,%3};\n"
        : "+f"(c[0]), "+f"(c[1]), "+f"(c[2]), "+f"(c[3])
        : "r"(a[0]), "r"(a[1]), "r"(a[2]), "r"(a[3]), "r"(b0), "r"(b1));
}

__device__ __forceinline__ void cp16(uint32_t dst, const void* src) {
    asm volatile("cp.async.cg.shared.global [%0], [%1], 16;" :: "r"(dst), "l"(src));
}

// ============================================================
// GEMM (fp16 in, fp32 out): C[m, z*512+n] = A[m,:].B_z[n,:] + bias
// 128 thr, 4 warps 2x2, warp 64x64, CTA 128x128, k-chunks of 32 halfs,
// 2-stage cp.async. Row stride 20 words (conflict-free frags).
// ============================================================
#define GPAD 20
#define AS_OFF(s) ((s) * 128 * GPAD)
#define BS_OFF(s) (2 * 128 * GPAD + (s) * 128 * GPAD)
#define GEMM_SMEM (4 * 128 * GPAD * 4)   // 40960 B

__global__ void __launch_bounds__(128, 3)
gemm_h_kernel(const __half* __restrict__ A,
              const __half* __restrict__ B0, const __half* __restrict__ B1,
              const __half* __restrict__ B2,
              const float* __restrict__ bias0, const float* __restrict__ bias1,
              const float* __restrict__ bias2,
              float* __restrict__ Cout, int ldc)
{
    const int z  = blockIdx.x >> 2;
    const int nb = blockIdx.x & 3;
    const __half* B   = (z == 0) ? B0 : (z == 1 ? B1 : B2);
    const float* bias = (z == 0) ? bias0 : (z == 1 ? bias1 : bias2);

    const int m0 = blockIdx.y * 128;
    const int n0 = nb * 128;

    extern __shared__ uint32_t smem_u[];
    const uint32_t sb = smem_u32(smem_u);

    const int tid  = threadIdx.x;
    const int warp = tid >> 5, lane = tid & 31;
    const int wm = warp & 1;
    const int wn = warp >> 1;
    const int g  = lane >> 2, tg = lane & 3;

    const __half* Ag = A + (size_t)(m0 + tid) * 512;
    const __half* Bg = B + (size_t)(n0 + tid) * 512;

    float acc[4][8][4];
#pragma unroll
    for (int i = 0; i < 4; i++)
#pragma unroll
        for (int j = 0; j < 8; j++)
#pragma unroll
            for (int r = 0; r < 4; r++) acc[i][j][r] = 0.f;

    // prologue: chunks 0,1
#pragma unroll
    for (int s = 0; s < 2; s++) {
        uint32_t ad = sb + (AS_OFF(s) + tid * GPAD) * 4;
        uint32_t bd = sb + (BS_OFF(s) + tid * GPAD) * 4;
#pragma unroll
        for (int i = 0; i < 4; i++) {
            cp16(ad + i * 16, Ag + s * 32 + i * 8);
            cp16(bd + i * 16, Bg + s * 32 + i * 8);
        }
        asm volatile("cp.async.commit_group;" ::: "memory");
    }

#pragma unroll 1
    for (int kc = 0; kc < 16; kc++) {
        const int s = kc & 1;
        if (kc < 15)
            asm volatile("cp.async.wait_group 1;" ::: "memory");
        else
            asm volatile("cp.async.wait_group 0;" ::: "memory");
        __syncthreads();

        const uint32_t* Ab = smem_u + AS_OFF(s);
        const uint32_t* Bb = smem_u + BS_OFF(s);
#pragma unroll
        for (int T = 0; T < 2; T++) {
            uint32_t af[4][4];
#pragma unroll
            for (int mi = 0; mi < 4; mi++) {
                const uint32_t* p = Ab + (wm * 64 + mi * 16 + g) * GPAD + 8 * T + tg;
                af[mi][0] = p[0];
                af[mi][1] = p[8 * GPAD];
                af[mi][2] = p[4];
                af[mi][3] = p[8 * GPAD + 4];
            }
#pragma unroll
            for (int ni = 0; ni < 8; ni++) {
                const uint32_t* q = Bb + (wn * 64 + ni * 8 + g) * GPAD + 8 * T + tg;
                uint32_t b0 = q[0], b1 = q[4];
#pragma unroll
                for (int mi = 0; mi < 4; mi++)
                    mma16(acc[mi][ni], af[mi], b0, b1);
            }
        }
        __syncthreads();

        if (kc + 2 < 16) {
            uint32_t ad = sb + (AS_OFF(s) + tid * GPAD) * 4;
            uint32_t bd = sb + (BS_OFF(s) + tid * GPAD) * 4;
#pragma unroll
            for (int i = 0; i < 4; i++) {
                cp16(ad + i * 16, Ag + (kc + 2) * 32 + i * 8);
                cp16(bd + i * 16, Bg + (kc + 2) * 32 + i * 8);
            }
            asm volatile("cp.async.commit_group;" ::: "memory");
        }
    }

    // epilogue (fp32 out + bias)
#pragma unroll
    for (int mi = 0; mi < 4; mi++) {
        int row = m0 + wm * 64 + mi * 16 + g;
#pragma unroll
        for (int ni = 0; ni < 8; ni++) {
            int ncol = n0 + wn * 64 + ni * 8 + 2 * tg;
            int gcol = z * 512 + ncol;
            float b0 = bias[ncol], b1 = bias[ncol + 1];
            float2 v0 = make_float2(acc[mi][ni][0] + b0, acc[mi][ni][1] + b1);
            float2 v1 = make_float2(acc[mi][ni][2] + b0, acc[mi][ni][3] + b1);
            *(float2*)(Cout + (size_t)row * ldc + gcol) = v0;
            *(float2*)(Cout + (size_t)(row + 8) * ldc + gcol) = v1;
        }
    }
}

// ============================================================
// conversion kernels (fp32 -> fp16 in global)
// ============================================================
__global__ void convert_x_kernel(const float* __restrict__ x, __half* __restrict__ o)
{
    size_t i = (size_t)blockIdx.x * 256 + threadIdx.x;
    float4 v = ((const float4*)x)[i];
    uint2 u = make_uint2(pack2h(v.x, v.y), pack2h(v.z, v.w));
    ((uint2*)o)[i] = u;
}

__global__ void convert_w_kernel(const float* __restrict__ w0, const float* __restrict__ w1,
                                 const float* __restrict__ w2, const float* __restrict__ w3,
                                 __half* __restrict__ o)
{
    size_t i = (size_t)blockIdx.x * 256 + threadIdx.x;   // 65536 float4 per matrix
    const float* srcs[4] = {w0, w1, w2, w3};
#pragma unroll
    for (int m = 0; m < 4; m++) {
        float4 v = ((const float4*)srcs[m])[i];
        uint2 u = make_uint2(pack2h(v.x, v.y), pack2h(v.z, v.w));
        ((uint2*)(o + (size_t)m * 262144))[i] = u;
    }
}

// ============================================================
// Attention (fp16 tensor cores, flash online softmax).
// One CTA per (b,h), 9 warps x 16 q-rows, strips of 16 keys.
// S = QK^T via 3-term fp16 split (k16 mmas); P stays in REGISTERS
// (S C-frag pair == PV A-frag); V^T in smem for PV B-frags.
// smem 32KB: ksh[144][20w] ksl[144][20w] vT[32][76w].
// ============================================================
#define KSP 20
#define VTP 76
#define KSH_OFF 0
#define KSL_OFF (144*KSP)
#define VT_OFF  (2*144*KSP)
#define ATT_SMEM ((2*144*KSP + 32*VTP) * 4)   // 32512 B

__global__ void __launch_bounds__(288, 2)
attn_kernel(const float* __restrict__ mask,
            const float* __restrict__ logit_scale,
            __half* __restrict__ attout)
{
    const int bh = blockIdx.x;
    const int b = bh >> 4;
    const int h = bh & 15;
    const int win = b & (NWIN - 1);

    const int tid = threadIdx.x;
    const int w = tid >> 5, lane = tid & 31;
    const int g = lane >> 2, tg = lane & 3;

    extern __shared__ uint32_t sm_u[];
    uint32_t* ksh = sm_u + KSH_OFF;
    uint32_t* ksl = sm_u + KSL_OFF;
    uint32_t* vT  = sm_u + VT_OFF;

    const float scale = expf(fminf(logit_scale[h], LOG100));

    const float* qbase = g_qkv + (size_t)(b * SEQ) * 1536 + h * 32;
    const float* kbase = qbase + 512;
    const float* vbase = qbase + 1024;

    // ---- load K (normalized, hi/lo fp16) and V^T (fp16), 2 threads/key ----
    {
        int r = tid >> 1, half_ = tid & 1;   // 288 = 144 keys x 2
        const float4* kr = (const float4*)(kbase + (size_t)r * 1536 + half_ * 16);
        float kv[16];
        float sq = 0.f;
#pragma unroll
        for (int i4 = 0; i4 < 4; i4++) {
            float4 f = kr[i4];
            kv[i4*4+0] = f.x; kv[i4*4+1] = f.y; kv[i4*4+2] = f.z; kv[i4*4+3] = f.w;
            sq += f.x*f.x + f.y*f.y + f.z*f.z + f.w*f.w;
        }
        sq += __shfl_xor_sync(0xffffffffu, sq, 1);
        float inv = 1.f / fmaxf(sqrtf(sq), 1e-12f);
#pragma unroll
        for (int j = 0; j < 8; j++) {
            float f0 = kv[2*j] * inv, f1 = kv[2*j+1] * inv;
            uint32_t hi = pack2h(f0, f1);
            float2 hf = unpack2h(hi);
            uint32_t lo = pack2h(f0 - hf.x, f1 - hf.y);
            int word = r * KSP + half_ * 8 + j;
            ksh[word] = hi;
            ksl[word] = lo;
        }
        // V^T: row d (0..31), key r; half element within word r>>1
        const float4* vr = (const float4*)(vbase + (size_t)r * 1536 + half_ * 16);
        __half* vh = (__half*)vT;
#pragma unroll
        for (int i4 = 0; i4 < 4; i4++) {
            float4 f = vr[i4];
            int d = half_ * 16 + i4 * 4;
            int widx = (r >> 1);
            int hidx = (r & 1);
            vh[((d + 0) * VTP + widx) * 2 + hidx] = __float2half(f.x);
            vh[((d + 1) * VTP + widx) * 2 + hidx] = __float2half(f.y);
            vh[((d + 2) * VTP + widx) * 2 + hidx] = __float2half(f.z);
            vh[((d + 3) * VTP + widx) * 2 + hidx] = __float2half(f.w);
        }
    }

    // ---- Q fragments from global: rows g, g+8 of this warp's 16-row tile ----
    // per k16 tile T: a0={rowA,d=16T+2tg,+1} a1={rowB,same} a2={rowA,16T+8+2tg,+1} a3={rowB,same}
    uint32_t ah[2][4], al[2][4];
    {
        const int rA = w * 16 + g;
        const int rB = rA + 8;
        const float* qA = qbase + (size_t)rA * 1536;
        const float* qB = qbase + (size_t)rB * 1536;
        float2 uA[2][2], uB[2][2];
        float sqA = 0.f, sqB = 0.f;
#pragma unroll
        for (int T = 0; T < 2; T++) {
#pragma unroll
            for (int p = 0; p < 2; p++) {
                int d = 16 * T + 8 * p + 2 * tg;
                uA[T][p] = *(const float2*)(qA + d);
                uB[T][p] = *(const float2*)(qB + d);
                sqA += uA[T][p].x * uA[T][p].x + uA[T][p].y * uA[T][p].y;
                sqB += uB[T][p].x * uB[T][p].x + uB[T][p].y * uB[T][p].y;
            }
        }
        sqA += __shfl_xor_sync(0xffffffffu, sqA, 1);
        sqA += __shfl_xor_sync(0xffffffffu, sqA, 2);
        sqB += __shfl_xor_sync(0xffffffffu, sqB, 1);
        sqB += __shfl_xor_sync(0xffffffffu, sqB, 2);
        float invA = scale / fmaxf(sqrtf(sqA), 1e-12f);
        float invB = scale / fmaxf(sqrtf(sqB), 1e-12f);
#pragma unroll
        for (int T = 0; T < 2; T++) {
#pragma unroll
            for (int p = 0; p < 2; p++) {
                float fax = uA[T][p].x * invA, fay = uA[T][p].y * invA;
                float fbx = uB[T][p].x * invB, fby = uB[T][p].y * invB;
                uint32_t hA = pack2h(fax, fay);
                uint32_t hB = pack2h(fbx, fby);
                float2 dA = unpack2h(hA), dB = unpack2h(hB);
                ah[T][2 * p]     = hA;
                ah[T][2 * p + 1] = hB;
                al[T][2 * p]     = pack2h(fax - dA.x, fay - dA.y);
                al[T][2 * p + 1] = pack2h(fbx - dB.x, fby - dB.y);
            }
        }
    }
    __syncthreads();   // K/V smem ready

    // ---- online softmax state ----
    const float NEG_INF = __int_as_float(0xff800000);
    float mr0 = NEG_INF, mr1 = NEG_INF;
    float sr0 = 0.f, sr1 = 0.f;
    float oc[4][4];
#pragma unroll
    for (int nt = 0; nt < 4; nt++)
#pragma unroll
        for (int r = 0; r < 4; r++) oc[nt][r] = 0.f;

    const float* mrow0 = mask + (size_t)win * SEQ * SEQ + (size_t)(w * 16 + g) * SEQ + 2 * tg;
    const float* mrow1 = mrow0 + (size_t)8 * SEQ;

    // ---- 9 strips of 16 keys ----
#pragma unroll 1
    for (int s = 0; s < 9; s++) {
        const int key0 = 16 * s;

        // S(s): 2 n-tiles x 2 k16 x 3-term
        float sacc[2][4];
#pragma unroll
        for (int nt = 0; nt < 2; nt++) {
#pragma unroll
            for (int r = 0; r < 4; r++) sacc[nt][r] = 0.f;
            const int krow = key0 + nt * 8 + g;
#pragma unroll
            for (int T = 0; T < 2; T++) {
                const uint32_t* p = ksh + krow * KSP + 8 * T + tg;
                uint32_t bh0 = p[0], bh1 = p[4];
                const uint32_t* q = ksl + krow * KSP + 8 * T + tg;
                uint32_t bl0 = q[0], bl1 = q[4];
                mma16(sacc[nt], ah[T], bh0, bh1);
                mma16(sacc[nt], al[T], bh0, bh1);
                mma16(sacc[nt], ah[T], bl0, bl1);
            }
        }

        // mask add + strip max
        float mx0 = NEG_INF, mx1 = NEG_INF;
#pragma unroll
        for (int nt = 0; nt < 2; nt++) {
            float2 m0 = *(const float2*)(mrow0 + key0 + nt * 8);
            float2 m1 = *(const float2*)(mrow1 + key0 + nt * 8);
            sacc[nt][0] += m0.x; sacc[nt][1] += m0.y;
            sacc[nt][2] += m1.x; sacc[nt][3] += m1.y;
            mx0 = fmaxf(mx0, fmaxf(sacc[nt][0], sacc[nt][1]));
            mx1 = fmaxf(mx1, fmaxf(sacc[nt][2], sacc[nt][3]));
        }
        mx0 = fmaxf(mx0, __shfl_xor_sync(0xffffffffu, mx0, 1));
        mx0 = fmaxf(mx0, __shfl_xor_sync(0xffffffffu, mx0, 2));
        mx1 = fmaxf(mx1, __shfl_xor_sync(0xffffffffu, mx1, 1));
        mx1 = fmaxf(mx1, __shfl_xor_sync(0xffffffffu, mx1, 2));

        float mn0 = fmaxf(mr0, mx0), mn1 = fmaxf(mr1, mx1);
        float f0 = __expf(mr0 - mn0), f1 = __expf(mr1 - mn1);
        mr0 = mn0; mr1 = mn1;
        sr0 *= f0; sr1 *= f1;
#pragma unroll
        for (int nt = 0; nt < 4; nt++) {
            oc[nt][0] *= f0; oc[nt][1] *= f0;
            oc[nt][2] *= f1; oc[nt][3] *= f1;
        }

        // exp -> P packed directly into PV A-fragment (registers only!)
        float p00 = __expf(sacc[0][0] - mn0), p01 = __expf(sacc[0][1] - mn0);
        float p02 = __expf(sacc[0][2] - mn1), p03 = __expf(sacc[0][3] - mn1);
        float p10 = __expf(sacc[1][0] - mn0), p11 = __expf(sacc[1][1] - mn0);
        float p12 = __expf(sacc[1][2] - mn1), p13 = __expf(sacc[1][3] - mn1);
        sr0 += p00 + p01 + p10 + p11;
        sr1 += p02 + p03 + p12 + p13;
        uint32_t a[4];
        a[0] = pack2h(p00, p01);   // row g,   keys key0+2tg,+1
        a[1] = pack2h(p02, p03);   // row g+8, keys key0+2tg,+1
        a[2] = pack2h(p10, p11);   // row g,   keys key0+8+2tg,+1
        a[3] = pack2h(p12, p13);   // row g+8, keys key0+8+2tg,+1

        // PV: oc[nt2] += P(16 keys) @ V^T
#pragma unroll
        for (int nt2 = 0; nt2 < 4; nt2++) {
            const uint32_t* vp = vT + (nt2 * 8 + g) * VTP + 8 * s + tg;
            uint32_t b0 = vp[0], b1 = vp[4];
            mma16(oc[nt2], a, b0, b1);
        }
    }

    // ---- finalize & store (fp16) ----
    sr0 += __shfl_xor_sync(0xffffffffu, sr0, 1);
    sr0 += __shfl_xor_sync(0xffffffffu, sr0, 2);
    sr1 += __shfl_xor_sync(0xffffffffu, sr1, 1);
    sr1 += __shfl_xor_sync(0xffffffffu, sr1, 2);
    float inv0 = 1.f / sr0, inv1 = 1.f / sr1;

    const int row0 = b * SEQ + w * 16 + g;
    uint32_t* out32 = (uint32_t*)attout;
#pragma unroll
    for (int nt = 0; nt < 4; nt++) {
        int col = h * 32 + nt * 8 + 2 * tg;
        out32[((size_t)row0 * 512 + col) >> 1] =
            pack2h(oc[nt][0] * inv0, oc[nt][1] * inv0);
        out32[(((size_t)(row0 + 8)) * 512 + col) >> 1] =
            pack2h(oc[nt][2] * inv1, oc[nt][3] * inv1);
    }
}

// ============================================================
// launch
// ============================================================
extern "C" void kernel_launch(void* const* d_in, const int* in_sizes, int n_in,
                              void* d_out, int out_size)
{
    (void)in_sizes; (void)n_in; (void)out_size;
    const float* x    = (const float*)d_in[0];
    const float* mask = (const float*)d_in[1];
    const float* Wq   = (const float*)d_in[2];
    const float* bq   = (const float*)d_in[3];
    const float* Wk   = (const float*)d_in[4];
    const float* bk   = (const float*)d_in[5];
    const float* Wv   = (const float*)d_in[6];
    const float* bv   = (const float*)d_in[7];
    const float* Wp   = (const float*)d_in[8];
    const float* bp   = (const float*)d_in[9];
    const float* ls   = (const float*)d_in[10];
    float* out = (float*)d_out;

    void *qkv_p = nullptr, *atth_p = nullptr, *xh_p = nullptr, *wh_p = nullptr;
    cudaGetSymbolAddress(&qkv_p, g_qkv);
    cudaGetSymbolAddress(&atth_p, g_atth);
    cudaGetSymbolAddress(&xh_p, g_xh);
    cudaGetSymbolAddress(&wh_p, g_wh);
    float*  qkv  = (float*)qkv_p;
    __half* atth = (__half*)atth_p;
    __half* xh   = (__half*)xh_p;
    __half* wh   = (__half*)wh_p;

    cudaFuncSetAttribute(gemm_h_kernel,
                         cudaFuncAttributeMaxDynamicSharedMemorySize, GEMM_SMEM);
    cudaFuncSetAttribute(attn_kernel,
                         cudaFuncAttributeMaxDynamicSharedMemorySize, ATT_SMEM);

    // 0) round inputs to fp16
    convert_x_kernel<<<MROWS * 512 / 4 / 256, 256>>>(x, xh);
    convert_w_kernel<<<256, 256>>>(Wq, Wk, Wv, Wp, wh);

    // 1) QKV projections: grid.x = 4 n-tiles * 3 z
    gemm_h_kernel<<<dim3(12, MROWS / 128), 128, GEMM_SMEM>>>(
        xh, wh, wh + 262144, wh + 2 * 262144, bq, bk, bv, qkv, 1536);

    // 2) attention (flash, fp16 mma, P in registers)
    attn_kernel<<<BW * NH, 288, ATT_SMEM>>>(mask, ls, atth);

    // 3) output projection
    gemm_h_kernel<<<dim3(4, MROWS / 128), 128, GEMM_SMEM>>>(
        atth, wh + 3 * 262144, wh + 3 * 262144, wh + 3 * 262144, bp, bp, bp, out, 512);
}

// round 9
// speedup vs baseline: 1.3956x; 1.0831x over previous
#include <cuda_runtime.h>
#include <cuda_fp16.h>
#include <cstdint>

// ---------------- problem constants ----------------
#define BW    1024
#define SEQ   144
#define CH    512
#define NH    16
#define DH    32
#define NWIN  64
#define MROWS (BW*SEQ)          // 147456
#define LOG100 4.6051701859880913680f

// ---------------- scratch ----------------
__device__ float  g_qkv[(size_t)MROWS * 1536];   // q|k|v per row (fp32)
__device__ __half g_atth[(size_t)MROWS * 512];   // attention out (fp16)
__device__ __half g_xh[(size_t)MROWS * 512];     // x in fp16
__device__ __half g_wh[4 * 512 * 512];           // weights fp16

// ---------------- helpers ----------------
__device__ __forceinline__ uint32_t pack2h(float x, float y) {
    __half2 h = __floats2half2_rn(x, y);
    return *(uint32_t*)&h;
}
__device__ __forceinline__ float2 unpack2h(uint32_t u) {
    __half2 h = *(__half2*)&u;
    return __half22float2(h);
}
__device__ __forceinline__ uint32_t smem_u32(const void* p) {
    uint32_t a;
    asm("{ .reg .u64 t; cvta.to.shared.u64 t, %1; cvt.u32.u64 %0, t; }" : "=r"(a) : "l"(p));
    return a;
}
__device__ __forceinline__ void mma16(float* c, const uint32_t* a, uint32_t b0, uint32_t b1) {
    asm volatile(
        "mma.sync.aligned.m16n8k16.row.col.f32.f16.f16.f32 "
        "{%0,%1,%2,%3}, {%4,%5,%6,%7}, {%8,%9}, {%0,%1,%2,%3};\n"
        : "+f"(c[0]), "+f"(c[1]), "+f"(c[2]), "+f"(c[3])
        : "r"(a[0]), "r"(a[1]), "r"(a[2]), "r"(a[3]), "r"(b0), "r"(b1));
}
__device__ __forceinline__ void ldsm4(uint32_t& r0, uint32_t& r1, uint32_t& r2, uint32_t& r3,
                                      uint32_t addr) {
    asm volatile("ldmatrix.sync.aligned.m8n8.x4.shared.b16 {%0,%1,%2,%3}, [%4];"
                 : "=r"(r0), "=r"(r1), "=r"(r2), "=r"(r3) : "r"(addr));
}
__device__ __forceinline__ void cp16(uint32_t dst, const void* src) {
    asm volatile("cp.async.cg.shared.global [%0], [%1], 16;" :: "r"(dst), "l"(src));
}

// ============================================================
// GEMM (fp16 in, fp32 out): 128 thr, warp 64x64, CTA 128x128,
// k-chunks of 32 halfs, 3-stage cp.async, ldmatrix fragments.
// GPAD=20 words/row (mult of 4, conflict-free for LDSM).
// ============================================================
#define GPAD 20
#define TILE_W (128 * GPAD)               // words per tile
#define GEMM_SMEM (6 * TILE_W * 4)        // 61440 B (3 stages x A,B)

__global__ void __launch_bounds__(128, 3)
gemm_h_kernel(const __half* __restrict__ A,
              const __half* __restrict__ B0, const __half* __restrict__ B1,
              const __half* __restrict__ B2,
              const float* __restrict__ bias0, const float* __restrict__ bias1,
              const float* __restrict__ bias2,
              float* __restrict__ Cout, int ldc)
{
    const int z  = blockIdx.x >> 2;
    const int nb = blockIdx.x & 3;
    const __half* B   = (z == 0) ? B0 : (z == 1 ? B1 : B2);
    const float* bias = (z == 0) ? bias0 : (z == 1 ? bias1 : bias2);

    const int m0 = blockIdx.y * 128;
    const int n0 = nb * 128;

    extern __shared__ uint32_t smem_u[];
    const uint32_t sb = smem_u32(smem_u);

    const int tid  = threadIdx.x;
    const int warp = tid >> 5, lane = tid & 31;
    const int wm = warp & 1;
    const int wn = warp >> 1;
    const int g  = lane >> 2, tg = lane & 3;

    const __half* Ag = A + (size_t)(m0 + tid) * 512;
    const __half* Bg = B + (size_t)(n0 + tid) * 512;

    // ldmatrix per-thread base offsets (bytes), within a tile
    const int lr16 = lane & 15, lk2 = lane >> 4;           // A map
    const uint32_t a_off = ((wm * 64 + lr16) * GPAD + lk2 * 4) * 4;
    const int br = (lane & 7) + ((lane >> 4) << 3), bk = (lane >> 3) & 1;  // B map
    const uint32_t b_off = ((wn * 64 + br) * GPAD + bk * 4) * 4;

    float acc[4][8][4];
#pragma unroll
    for (int i = 0; i < 4; i++)
#pragma unroll
        for (int j = 0; j < 8; j++)
#pragma unroll
            for (int r = 0; r < 4; r++) acc[i][j][r] = 0.f;

    // prologue: fill stages 0,1 (chunks 0,1)
#pragma unroll
    for (int s = 0; s < 2; s++) {
        uint32_t ad = sb + (2 * s * TILE_W + tid * GPAD) * 4;
        uint32_t bd = ad + TILE_W * 4;
#pragma unroll
        for (int i = 0; i < 4; i++) {
            cp16(ad + i * 16, Ag + s * 32 + i * 8);
            cp16(bd + i * 16, Bg + s * 32 + i * 8);
        }
        asm volatile("cp.async.commit_group;" ::: "memory");
    }

#pragma unroll 1
    for (int kc = 0; kc < 16; kc++) {
        if (kc < 14)
            asm volatile("cp.async.wait_group 1;" ::: "memory");
        else
            asm volatile("cp.async.wait_group 0;" ::: "memory");
        __syncthreads();

        const int st = kc - (kc / 3) * 3;            // kc % 3
        const uint32_t abase = sb + 2 * st * TILE_W * 4 + a_off;
        const uint32_t bbase = abase + TILE_W * 4 - a_off + b_off;  // = stage B + b_off

#pragma unroll
        for (int T = 0; T < 2; T++) {
            uint32_t af[4][4], bf[4][4];
#pragma unroll
            for (int mi = 0; mi < 4; mi++)
                ldsm4(af[mi][0], af[mi][1], af[mi][2], af[mi][3],
                      abase + (mi * 16 * GPAD + T * 8) * 4);
#pragma unroll
            for (int np = 0; np < 4; np++)
                ldsm4(bf[np][0], bf[np][1], bf[np][2], bf[np][3],
                      bbase + (np * 16 * GPAD + T * 8) * 4);
#pragma unroll
            for (int np = 0; np < 4; np++)
#pragma unroll
                for (int mi = 0; mi < 4; mi++) {
                    mma16(acc[mi][2 * np],     af[mi], bf[np][0], bf[np][1]);
                    mma16(acc[mi][2 * np + 1], af[mi], bf[np][2], bf[np][3]);
                }
        }

        // fill chunk kc+2 into stage (kc-1)%3 (read last chunk; all warps past it)
        if (kc + 2 < 16) {
            int fs = kc + 2 - ((kc + 2) / 3) * 3;
            uint32_t ad = sb + (2 * fs * TILE_W + tid * GPAD) * 4;
            uint32_t bd = ad + TILE_W * 4;
#pragma unroll
            for (int i = 0; i < 4; i++) {
                cp16(ad + i * 16, Ag + (kc + 2) * 32 + i * 8);
                cp16(bd + i * 16, Bg + (kc + 2) * 32 + i * 8);
            }
            asm volatile("cp.async.commit_group;" ::: "memory");
        }
    }

    // epilogue (fp32 out + bias)
#pragma unroll
    for (int mi = 0; mi < 4; mi++) {
        int row = m0 + wm * 64 + mi * 16 + g;
#pragma unroll
        for (int ni = 0; ni < 8; ni++) {
            int ncol = n0 + wn * 64 + ni * 8 + 2 * tg;
            int gcol = z * 512 + ncol;
            float b0 = bias[ncol], b1 = bias[ncol + 1];
            float2 v0 = make_float2(acc[mi][ni][0] + b0, acc[mi][ni][1] + b1);
            float2 v1 = make_float2(acc[mi][ni][2] + b0, acc[mi][ni][3] + b1);
            *(float2*)(Cout + (size_t)row * ldc + gcol) = v0;
            *(float2*)(Cout + (size_t)(row + 8) * ldc + gcol) = v1;
        }
    }
}

// ============================================================
// conversion kernels
// ============================================================
__global__ void convert_x_kernel(const float* __restrict__ x, __half* __restrict__ o)
{
    size_t i = (size_t)blockIdx.x * 256 + threadIdx.x;
    float4 v = ((const float4*)x)[i];
    ((uint2*)o)[i] = make_uint2(pack2h(v.x, v.y), pack2h(v.z, v.w));
}

__global__ void convert_w_kernel(const float* __restrict__ w0, const float* __restrict__ w1,
                                 const float* __restrict__ w2, const float* __restrict__ w3,
                                 __half* __restrict__ o)
{
    size_t i = (size_t)blockIdx.x * 256 + threadIdx.x;
    const float* srcs[4] = {w0, w1, w2, w3};
#pragma unroll
    for (int m = 0; m < 4; m++) {
        float4 v = ((const float4*)srcs[m])[i];
        ((uint2*)(o + (size_t)m * 262144))[i] = make_uint2(pack2h(v.x, v.y), pack2h(v.z, v.w));
    }
}

// ============================================================
// Attention (fp16, flash): 5 warps x 32 q-rows (mi=2), rows padded
// 144->160 (warp4/mi1 phantom). 9 strips of 16 keys. S via 3-term
// fp16 split; K and V fragments via ldmatrix.x4; P in registers.
// ============================================================
#define KSP 20
#define VTP 76
#define ATT_SMEM ((2*144*KSP + 32*VTP) * 4)   // 32512 B

__global__ void __launch_bounds__(160, 3)
attn_kernel(const float* __restrict__ mask,
            const float* __restrict__ logit_scale,
            __half* __restrict__ attout)
{
    const int bh = blockIdx.x;
    const int b = bh >> 4;
    const int h = bh & 15;
    const int win = b & (NWIN - 1);

    const int tid = threadIdx.x;
    const int w = tid >> 5, lane = tid & 31;
    const int g = lane >> 2, tg = lane & 3;

    extern __shared__ uint32_t sm_u[];
    uint32_t* ksh = sm_u;                    // [144][20]
    uint32_t* ksl = ksh + 144 * KSP;         // [144][20]
    uint32_t* vT  = ksl + 144 * KSP;         // [32][76]
    const uint32_t sb = smem_u32(sm_u);
    const uint32_t ksl_b = sb + 144 * KSP * 4;
    const uint32_t vT_b  = ksl_b + 144 * KSP * 4;

    const float scale = expf(fminf(logit_scale[h], LOG100));

    const float* qbase = g_qkv + (size_t)(b * SEQ) * 1536 + h * 32;
    const float* kbase = qbase + 512;
    const float* vbase = qbase + 1024;

    // ---- load K (normalized hi/lo fp16) + V^T, 2 threads per key ----
#pragma unroll
    for (int t = tid; t < 288; t += 160) {
        int r = t >> 1, half_ = t & 1;
        const float4* kr = (const float4*)(kbase + (size_t)r * 1536 + half_ * 16);
        float kv[16];
        float sq = 0.f;
#pragma unroll
        for (int i4 = 0; i4 < 4; i4++) {
            float4 f = kr[i4];
            kv[i4*4+0] = f.x; kv[i4*4+1] = f.y; kv[i4*4+2] = f.z; kv[i4*4+3] = f.w;
            sq += f.x*f.x + f.y*f.y + f.z*f.z + f.w*f.w;
        }
        sq += __shfl_xor_sync(0xffffffffu, sq, 1);
        float inv = 1.f / fmaxf(sqrtf(sq), 1e-12f);
#pragma unroll
        for (int j = 0; j < 8; j++) {
            float f0 = kv[2*j] * inv, f1 = kv[2*j+1] * inv;
            uint32_t hi = pack2h(f0, f1);
            float2 hf = unpack2h(hi);
            int word = r * KSP + half_ * 8 + j;
            ksh[word] = hi;
            ksl[word] = pack2h(f0 - hf.x, f1 - hf.y);
        }
        const float4* vr = (const float4*)(vbase + (size_t)r * 1536 + half_ * 16);
        __half* vh = (__half*)vT;
#pragma unroll
        for (int i4 = 0; i4 < 4; i4++) {
            float4 f = vr[i4];
            int d = half_ * 16 + i4 * 4;
            int widx = r >> 1, hidx = r & 1;
            vh[((d + 0) * VTP + widx) * 2 + hidx] = __float2half(f.x);
            vh[((d + 1) * VTP + widx) * 2 + hidx] = __float2half(f.y);
            vh[((d + 2) * VTP + widx) * 2 + hidx] = __float2half(f.z);
            vh[((d + 3) * VTP + widx) * 2 + hidx] = __float2half(f.w);
        }
    }

    // ---- Q fragments (2 mi tiles), hi/lo split, from global ----
    uint32_t ah[2][2][4], al[2][2][4];
#pragma unroll
    for (int mi = 0; mi < 2; mi++) {
        const int rA = w * 32 + mi * 16 + g;
        const int rB = rA + 8;
        const float* qA = qbase + (size_t)rA * 1536;
        const float* qB = qbase + (size_t)rB * 1536;
        float2 uA[2][2], uB[2][2];
        float sqA = 0.f, sqB = 0.f;
#pragma unroll
        for (int T = 0; T < 2; T++)
#pragma unroll
            for (int p = 0; p < 2; p++) {
                int d = 16 * T + 8 * p + 2 * tg;
                uA[T][p] = (rA < 144) ? *(const float2*)(qA + d) : make_float2(0.f, 0.f);
                uB[T][p] = (rB < 144) ? *(const float2*)(qB + d) : make_float2(0.f, 0.f);
                sqA += uA[T][p].x * uA[T][p].x + uA[T][p].y * uA[T][p].y;
                sqB += uB[T][p].x * uB[T][p].x + uB[T][p].y * uB[T][p].y;
            }
        sqA += __shfl_xor_sync(0xffffffffu, sqA, 1);
        sqA += __shfl_xor_sync(0xffffffffu, sqA, 2);
        sqB += __shfl_xor_sync(0xffffffffu, sqB, 1);
        sqB += __shfl_xor_sync(0xffffffffu, sqB, 2);
        float invA = scale / fmaxf(sqrtf(sqA), 1e-12f);
        float invB = scale / fmaxf(sqrtf(sqB), 1e-12f);
#pragma unroll
        for (int T = 0; T < 2; T++)
#pragma unroll
            for (int p = 0; p < 2; p++) {
                float fax = uA[T][p].x * invA, fay = uA[T][p].y * invA;
                float fbx = uB[T][p].x * invB, fby = uB[T][p].y * invB;
                uint32_t hA = pack2h(fax, fay);
                uint32_t hB = pack2h(fbx, fby);
                float2 dA = unpack2h(hA), dB = unpack2h(hB);
                ah[mi][T][2 * p]     = hA;
                ah[mi][T][2 * p + 1] = hB;
                al[mi][T][2 * p]     = pack2h(fax - dA.x, fay - dA.y);
                al[mi][T][2 * p + 1] = pack2h(fbx - dB.x, fby - dB.y);
            }
    }
    __syncthreads();

    // ---- ldmatrix per-thread offsets ----
    const int kr8 = (lane & 7) + ((lane >> 4) << 3);   // key/row select
    const int kb  = (lane >> 3) & 1;                   // k-block select
    const uint32_t koff = (uint32_t)(kr8 * KSP + kb * 4) * 4;
    const uint32_t voff = (uint32_t)(kr8 * VTP + kb * 4) * 4;

    // ---- online softmax state ----
    const float NEG_INF = __int_as_float(0xff800000);
    float mr[2][2] = {{NEG_INF, NEG_INF}, {NEG_INF, NEG_INF}};
    float sr[2][2] = {{0.f, 0.f}, {0.f, 0.f}};
    float oc[2][4][4];
#pragma unroll
    for (int mi = 0; mi < 2; mi++)
#pragma unroll
        for (int nt = 0; nt < 4; nt++)
#pragma unroll
            for (int r = 0; r < 4; r++) oc[mi][nt][r] = 0.f;

    const float* mbase = mask + (size_t)win * SEQ * SEQ + 2 * tg;
    const float* mrow[2][2];
#pragma unroll
    for (int mi = 0; mi < 2; mi++) {
        int rA = w * 32 + mi * 16 + g;
        int rB = rA + 8;
        mrow[mi][0] = mbase + (size_t)(rA < 144 ? rA : 143) * SEQ;
        mrow[mi][1] = mbase + (size_t)(rB < 144 ? rB : 143) * SEQ;
    }

    // ---- 9 strips of 16 keys ----
#pragma unroll 1
    for (int s = 0; s < 9; s++) {
        const int key0 = 16 * s;

        // S: K frags via ldmatrix (hi & lo), 3-term split
        float sacc[2][2][4];
#pragma unroll
        for (int mi = 0; mi < 2; mi++)
#pragma unroll
            for (int nt = 0; nt < 2; nt++)
#pragma unroll
                for (int r = 0; r < 4; r++) sacc[mi][nt][r] = 0.f;

#pragma unroll
        for (int T = 0; T < 2; T++) {
            uint32_t kh[4], kl[4];
            uint32_t base = (uint32_t)(key0 * KSP + T * 8) * 4 + koff;
            ldsm4(kh[0], kh[1], kh[2], kh[3], sb + base);
            ldsm4(kl[0], kl[1], kl[2], kl[3], ksl_b + base);
#pragma unroll
            for (int mi = 0; mi < 2; mi++) {
                mma16(sacc[mi][0], ah[mi][T], kh[0], kh[1]);
                mma16(sacc[mi][0], al[mi][T], kh[0], kh[1]);
                mma16(sacc[mi][0], ah[mi][T], kl[0], kl[1]);
                mma16(sacc[mi][1], ah[mi][T], kh[2], kh[3]);
                mma16(sacc[mi][1], al[mi][T], kh[2], kh[3]);
                mma16(sacc[mi][1], ah[mi][T], kl[2], kl[3]);
            }
        }

        // masks + strip max + online update + P pack (per mi)
        uint32_t pa[2][4];
#pragma unroll
        for (int mi = 0; mi < 2; mi++) {
            float mx0 = NEG_INF, mx1 = NEG_INF;
#pragma unroll
            for (int nt = 0; nt < 2; nt++) {
                float2 m0 = *(const float2*)(mrow[mi][0] + key0 + nt * 8);
                float2 m1 = *(const float2*)(mrow[mi][1] + key0 + nt * 8);
                sacc[mi][nt][0] += m0.x; sacc[mi][nt][1] += m0.y;
                sacc[mi][nt][2] += m1.x; sacc[mi][nt][3] += m1.y;
                mx0 = fmaxf(mx0, fmaxf(sacc[mi][nt][0], sacc[mi][nt][1]));
                mx1 = fmaxf(mx1, fmaxf(sacc[mi][nt][2], sacc[mi][nt][3]));
            }
            mx0 = fmaxf(mx0, __shfl_xor_sync(0xffffffffu, mx0, 1));
            mx0 = fmaxf(mx0, __shfl_xor_sync(0xffffffffu, mx0, 2));
            mx1 = fmaxf(mx1, __shfl_xor_sync(0xffffffffu, mx1, 1));
            mx1 = fmaxf(mx1, __shfl_xor_sync(0xffffffffu, mx1, 2));

            float mn0 = fmaxf(mr[mi][0], mx0), mn1 = fmaxf(mr[mi][1], mx1);
            float f0 = __expf(mr[mi][0] - mn0), f1 = __expf(mr[mi][1] - mn1);
            mr[mi][0] = mn0; mr[mi][1] = mn1;
            sr[mi][0] *= f0; sr[mi][1] *= f1;
#pragma unroll
            for (int nt = 0; nt < 4; nt++) {
                oc[mi][nt][0] *= f0; oc[mi][nt][1] *= f0;
                oc[mi][nt][2] *= f1; oc[mi][nt][3] *= f1;
            }

            float p00 = __expf(sacc[mi][0][0] - mn0), p01 = __expf(sacc[mi][0][1] - mn0);
            float p02 = __expf(sacc[mi][0][2] - mn1), p03 = __expf(sacc[mi][0][3] - mn1);
            float p10 = __expf(sacc[mi][1][0] - mn0), p11 = __expf(sacc[mi][1][1] - mn0);
            float p12 = __expf(sacc[mi][1][2] - mn1), p13 = __expf(sacc[mi][1][3] - mn1);
            sr[mi][0] += p00 + p01 + p10 + p11;
            sr[mi][1] += p02 + p03 + p12 + p13;
            pa[mi][0] = pack2h(p00, p01);
            pa[mi][1] = pack2h(p02, p03);
            pa[mi][2] = pack2h(p10, p11);
            pa[mi][3] = pack2h(p12, p13);
        }

        // PV: V frags via ldmatrix (2 x4 per strip cover nt2=0..3)
#pragma unroll
        for (int np = 0; np < 2; np++) {
            uint32_t vb[4];
            ldsm4(vb[0], vb[1], vb[2], vb[3],
                  vT_b + (uint32_t)(np * 16 * VTP + s * 8) * 4 + voff);
#pragma unroll
            for (int mi = 0; mi < 2; mi++) {
                mma16(oc[mi][2 * np],     pa[mi], vb[0], vb[1]);
                mma16(oc[mi][2 * np + 1], pa[mi], vb[2], vb[3]);
            }
        }
    }

    // ---- finalize & store ----
    uint32_t* out32 = (uint32_t*)attout;
#pragma unroll
    for (int mi = 0; mi < 2; mi++) {
        float s0 = sr[mi][0], s1 = sr[mi][1];
        s0 += __shfl_xor_sync(0xffffffffu, s0, 1);
        s0 += __shfl_xor_sync(0xffffffffu, s0, 2);
        s1 += __shfl_xor_sync(0xffffffffu, s1, 1);
        s1 += __shfl_xor_sync(0xffffffffu, s1, 2);
        float inv0 = 1.f / s0, inv1 = 1.f / s1;

        const int rA = w * 32 + mi * 16 + g;
        if (rA < 144) {
            const int row0 = b * SEQ + rA;
#pragma unroll
            for (int nt = 0; nt < 4; nt++) {
                int col = h * 32 + nt * 8 + 2 * tg;
                out32[((size_t)row0 * 512 + col) >> 1] =
                    pack2h(oc[mi][nt][0] * inv0, oc[mi][nt][1] * inv0);
                out32[(((size_t)(row0 + 8)) * 512 + col) >> 1] =
                    pack2h(oc[mi][nt][2] * inv1, oc[mi][nt][3] * inv1);
            }
        }
    }
}

// ============================================================
// launch
// ============================================================
extern "C" void kernel_launch(void* const* d_in, const int* in_sizes, int n_in,
                              void* d_out, int out_size)
{
    (void)in_sizes; (void)n_in; (void)out_size;
    const float* x    = (const float*)d_in[0];
    const float* mask = (const float*)d_in[1];
    const float* Wq   = (const float*)d_in[2];
    const float* bq   = (const float*)d_in[3];
    const float* Wk   = (const float*)d_in[4];
    const float* bk   = (const float*)d_in[5];
    const float* Wv   = (const float*)d_in[6];
    const float* bv   = (const float*)d_in[7];
    const float* Wp   = (const float*)d_in[8];
    const float* bp   = (const float*)d_in[9];
    const float* ls   = (const float*)d_in[10];
    float* out = (float*)d_out;

    void *qkv_p = nullptr, *atth_p = nullptr, *xh_p = nullptr, *wh_p = nullptr;
    cudaGetSymbolAddress(&qkv_p, g_qkv);
    cudaGetSymbolAddress(&atth_p, g_atth);
    cudaGetSymbolAddress(&xh_p, g_xh);
    cudaGetSymbolAddress(&wh_p, g_wh);
    float*  qkv  = (float*)qkv_p;
    __half* atth = (__half*)atth_p;
    __half* xh   = (__half*)xh_p;
    __half* wh   = (__half*)wh_p;

    cudaFuncSetAttribute(gemm_h_kernel,
                         cudaFuncAttributeMaxDynamicSharedMemorySize, GEMM_SMEM);
    cudaFuncSetAttribute(attn_kernel,
                         cudaFuncAttributeMaxDynamicSharedMemorySize, ATT_SMEM);

    // 0) fp32 -> fp16
    convert_x_kernel<<<MROWS * 512 / 4 / 256, 256>>>(x, xh);
    convert_w_kernel<<<256, 256>>>(Wq, Wk, Wv, Wp, wh);

    // 1) QKV projections
    gemm_h_kernel<<<dim3(12, MROWS / 128), 128, GEMM_SMEM>>>(
        xh, wh, wh + 262144, wh + 2 * 262144, bq, bk, bv, qkv, 1536);

    // 2) attention
    attn_kernel<<<BW * NH, 160, ATT_SMEM>>>(mask, ls, atth);

    // 3) output projection
    gemm_h_kernel<<<dim3(4, MROWS / 128), 128, GEMM_SMEM>>>(
        atth, wh + 3 * 262144, wh + 3 * 262144, wh + 3 * 262144, bp, bp, bp, out, 512);
}